// round 2
// baseline (speedup 1.0000x reference)
#include <cuda_runtime.h>

// ---------------------------------------------------------------------------
// GRU recurrence (T-1 = 511 steps) + per-step decode/BCE loss, fused into one
// persistent cooperative-style kernel with a software grid barrier.
//
//   per step: gi = x_t @ W_ih^T + b_ih ; gh = h @ W_hh^T + b_hh
//             r = sig(gi_r+gh_r), z = sig(gi_z+gh_z), n = tanh(gi_n + r*gh_n)
//             h' = (1-z)*n + z*h ; loss += BCE(sigmoid(h'@W_dec + b_dec), gt)
//
// Layout: 128 CTAs = 8 batch-groups (32 rows) x 16 unit-groups (16 hidden
// units = 48 gate columns). W slice lives in smem for the whole kernel.
// ---------------------------------------------------------------------------

#define T_SEQ   512
#define BATCH   256
#define IN_DIM  128
#define HID     256
#define STEPS   (T_SEQ - 1)      // 511

#define GRID_X   128
#define NTHREADS 256
#define BM       32              // batch rows per CTA
#define NU       16              // hidden units per CTA (=> 48 gate cols)
#define SA_STR   388             // padded row stride (floats), 388%32=4 -> no conflicts
#define NK4      96              // 384 floats / 4
#define NK4_H    64              // first 256 floats = h part

#define SMEM_FLOATS (48 * SA_STR + BM * SA_STR + 64 + 256)
#define SMEM_BYTES  (SMEM_FLOATS * 4)

__device__ float    g_h[2][BATCH * HID];
__device__ unsigned g_arrive;
__device__ unsigned g_release;

__global__ void gru_init_kernel(float* out) {
    int i = blockIdx.x * blockDim.x + threadIdx.x;
    if (i == 0) { g_arrive = 0u; g_release = 0u; out[0] = 0.0f; }
    for (int j = i; j < BATCH * HID; j += gridDim.x * blockDim.x)
        g_h[0][j] = 0.0f;
}

__device__ __forceinline__ void grid_barrier(unsigned gen) {
    __syncthreads();
    if (threadIdx.x == 0) {
        __threadfence();
        unsigned a = atomicAdd(&g_arrive, 1u) + 1u;
        if (a == gen * (unsigned)GRID_X) {
            atomicExch(&g_release, gen);             // release
        } else {
            volatile unsigned* rel = &g_release;
            while (*rel < gen) __nanosleep(32);
        }
        __threadfence();
    }
    __syncthreads();
}

__device__ __forceinline__ float sigmoidf_fast(float v) {
    return 1.0f / (1.0f + __expf(-v));
}

__global__ __launch_bounds__(NTHREADS)
void gru_main_kernel(const float* __restrict__ x,
                     const float* __restrict__ gt,
                     const float* __restrict__ W_ih,
                     const float* __restrict__ W_hh,
                     const float* __restrict__ b_ih,
                     const float* __restrict__ b_hh,
                     const float* __restrict__ W_dec,
                     const float* __restrict__ b_dec,
                     float* __restrict__ out)
{
    extern __shared__ float smem[];
    float* sW  = smem;                     // [48][SA_STR]  weight slice
    float* sA  = sW + 48 * SA_STR;         // [BM][SA_STR]  [h_prev | x_t]
    float* sb  = sA + BM * SA_STR;         // 64: r(16) z(16) n_i(16) n_h(16)
    float* sWd = sb + 64;                  // 256: W_dec

    const int tid = threadIdx.x;
    const int cb  = blockIdx.x & 7;        // batch group
    const int cu  = blockIdx.x >> 3;       // unit group
    const int B0  = cb * BM;
    const int U0  = cu * NU;

    const int u  = tid & 15;               // hidden unit within group
    const int bp = tid >> 4;               // batch pair 0..15
    const int b0 = bp * 2;
    const int b1 = b0 + 1;

    // ---- persistent loads: W slice (48 rows x [W_hh | W_ih]), biases, W_dec
    for (int idx = tid; idx < 48 * NK4; idx += NTHREADS) {
        int c  = idx / NK4;
        int k4 = idx - c * NK4;
        int g  = c >> 4;
        int uu = c & 15;
        int wrow = g * HID + U0 + uu;
        float4 v;
        if (k4 < NK4_H) v = ((const float4*)W_hh)[wrow * 64 + k4];
        else            v = ((const float4*)W_ih)[wrow * 32 + (k4 - NK4_H)];
        ((float4*)(sW + c * SA_STR))[k4] = v;
    }
    if (tid < 16) {
        sb[tid]      = b_ih[U0 + tid]       + b_hh[U0 + tid];        // r: fold
        sb[16 + tid] = b_ih[HID + U0 + tid] + b_hh[HID + U0 + tid];  // z: fold
        sb[32 + tid] = b_ih[2 * HID + U0 + tid];                     // n, x-side
        sb[48 + tid] = b_hh[2 * HID + U0 + tid];                     // n, h-side
    }
    sWd[tid] = W_dec[tid];
    __syncthreads();

    const float bdec = b_dec[0];
    float loss_local = 0.0f;
    int p = 0;

    for (int t = 0; t < STEPS; ++t) {
        // ---- stage A = [h_prev | x_t] for this CTA's 32 batch rows
        for (int idx = tid; idx < BM * NK4; idx += NTHREADS) {
            int r  = idx / NK4;
            int k4 = idx - r * NK4;
            float4 v;
            if (k4 < NK4_H)
                v = ((const float4*)g_h[p])[(B0 + r) * 64 + k4];
            else
                v = ((const float4*)x)[((size_t)t * BATCH + B0 + r) * 32 + (k4 - NK4_H)];
            ((float4*)(sA + r * SA_STR))[k4] = v;
        }
        __syncthreads();

        // ---- deferred loss for step t-1 (h_prev == h_new(t-1)), unit-group 0
        if (cu == 0 && t > 0) {
            int row  = tid >> 3;
            int part = tid & 7;
            const float4* ar = (const float4*)(sA + row * SA_STR);
            const float4* wd = (const float4*)sWd;
            float s = 0.0f;
            #pragma unroll
            for (int j = 0; j < 8; ++j) {
                float4 a = ar[part * 8 + j];
                float4 w = wd[part * 8 + j];
                s += a.x * w.x + a.y * w.y + a.z * w.z + a.w * w.w;
            }
            s += __shfl_down_sync(0xffffffffu, s, 4);
            s += __shfl_down_sync(0xffffffffu, s, 2);
            s += __shfl_down_sync(0xffffffffu, s, 1);
            if (part == 0) {
                float l = s + bdec;
                float g = gt[t * BATCH + B0 + row];
                // BCE(sum) stable: softplus(l) - g*l
                loss_local += fmaxf(l, 0.0f) + log1pf(__expf(-fabsf(l))) - g * l;
            }
        }

        // ---- per-step GEMM: 2 batch rows x {r,z,n} for unit u, K = 384
        float ar0 = 0.f, az0 = 0.f, anh0 = 0.f, ani0 = 0.f;
        float ar1 = 0.f, az1 = 0.f, anh1 = 0.f, ani1 = 0.f;
        const float4* A0 = (const float4*)(sA + b0 * SA_STR);
        const float4* A1 = (const float4*)(sA + b1 * SA_STR);
        const float4* Wr = (const float4*)(sW + u * SA_STR);
        const float4* Wz = (const float4*)(sW + (16 + u) * SA_STR);
        const float4* Wn = (const float4*)(sW + (32 + u) * SA_STR);

        #pragma unroll 8
        for (int k4 = 0; k4 < NK4_H; ++k4) {        // h part -> r, z, n_h
            float4 h0 = A0[k4], h1 = A1[k4];
            float4 wr = Wr[k4], wz = Wz[k4], wn = Wn[k4];
            ar0  = fmaf(h0.x, wr.x, ar0);  ar0  = fmaf(h0.y, wr.y, ar0);
            ar0  = fmaf(h0.z, wr.z, ar0);  ar0  = fmaf(h0.w, wr.w, ar0);
            az0  = fmaf(h0.x, wz.x, az0);  az0  = fmaf(h0.y, wz.y, az0);
            az0  = fmaf(h0.z, wz.z, az0);  az0  = fmaf(h0.w, wz.w, az0);
            anh0 = fmaf(h0.x, wn.x, anh0); anh0 = fmaf(h0.y, wn.y, anh0);
            anh0 = fmaf(h0.z, wn.z, anh0); anh0 = fmaf(h0.w, wn.w, anh0);
            ar1  = fmaf(h1.x, wr.x, ar1);  ar1  = fmaf(h1.y, wr.y, ar1);
            ar1  = fmaf(h1.z, wr.z, ar1);  ar1  = fmaf(h1.w, wr.w, ar1);
            az1  = fmaf(h1.x, wz.x, az1);  az1  = fmaf(h1.y, wz.y, az1);
            az1  = fmaf(h1.z, wz.z, az1);  az1  = fmaf(h1.w, wz.w, az1);
            anh1 = fmaf(h1.x, wn.x, anh1); anh1 = fmaf(h1.y, wn.y, anh1);
            anh1 = fmaf(h1.z, wn.z, anh1); anh1 = fmaf(h1.w, wn.w, anh1);
        }
        #pragma unroll 8
        for (int k4 = NK4_H; k4 < NK4; ++k4) {      // x part -> r, z, n_i
            float4 h0 = A0[k4], h1 = A1[k4];
            float4 wr = Wr[k4], wz = Wz[k4], wn = Wn[k4];
            ar0  = fmaf(h0.x, wr.x, ar0);  ar0  = fmaf(h0.y, wr.y, ar0);
            ar0  = fmaf(h0.z, wr.z, ar0);  ar0  = fmaf(h0.w, wr.w, ar0);
            az0  = fmaf(h0.x, wz.x, az0);  az0  = fmaf(h0.y, wz.y, az0);
            az0  = fmaf(h0.z, wz.z, az0);  az0  = fmaf(h0.w, wz.w, az0);
            ani0 = fmaf(h0.x, wn.x, ani0); ani0 = fmaf(h0.y, wn.y, ani0);
            ani0 = fmaf(h0.z, wn.z, ani0); ani0 = fmaf(h0.w, wn.w, ani0);
            ar1  = fmaf(h1.x, wr.x, ar1);  ar1  = fmaf(h1.y, wr.y, ar1);
            ar1  = fmaf(h1.z, wr.z, ar1);  ar1  = fmaf(h1.w, wr.w, ar1);
            az1  = fmaf(h1.x, wz.x, az1);  az1  = fmaf(h1.y, wz.y, az1);
            az1  = fmaf(h1.z, wz.z, az1);  az1  = fmaf(h1.w, wz.w, az1);
            ani1 = fmaf(h1.x, wn.x, ani1); ani1 = fmaf(h1.y, wn.y, ani1);
            ani1 = fmaf(h1.z, wn.z, ani1); ani1 = fmaf(h1.w, wn.w, ani1);
        }

        // ---- GRU epilogue
        {
            float br = sb[u], bz = sb[16 + u], bni = sb[32 + u], bnh = sb[48 + u];
            float hp0 = sA[b0 * SA_STR + U0 + u];
            float hp1 = sA[b1 * SA_STR + U0 + u];

            float r0 = sigmoidf_fast(ar0 + br);
            float z0 = sigmoidf_fast(az0 + bz);
            float n0 = tanhf(ani0 + bni + r0 * (anh0 + bnh));
            float hn0 = n0 + z0 * (hp0 - n0);

            float r1 = sigmoidf_fast(ar1 + br);
            float z1 = sigmoidf_fast(az1 + bz);
            float n1 = tanhf(ani1 + bni + r1 * (anh1 + bnh));
            float hn1 = n1 + z1 * (hp1 - n1);

            float* dst = g_h[p ^ 1];
            dst[(B0 + b0) * HID + U0 + u] = hn0;
            dst[(B0 + b1) * HID + U0 + u] = hn1;
        }

        grid_barrier((unsigned)(t + 1));
        p ^= 1;
    }

    // ---- loss for the final step (t = STEPS-1) using gt[STEPS]
    if (cu == 0) {
        int row  = tid >> 3;
        int part = tid & 7;
        const float4* hr = (const float4*)(g_h[p] + (B0 + row) * HID);
        const float4* wd = (const float4*)sWd;
        float s = 0.0f;
        #pragma unroll
        for (int j = 0; j < 8; ++j) {
            float4 a = hr[part * 8 + j];
            float4 w = wd[part * 8 + j];
            s += a.x * w.x + a.y * w.y + a.z * w.z + a.w * w.w;
        }
        s += __shfl_down_sync(0xffffffffu, s, 4);
        s += __shfl_down_sync(0xffffffffu, s, 2);
        s += __shfl_down_sync(0xffffffffu, s, 1);
        if (part == 0) {
            float l = s + bdec;
            float g = gt[STEPS * BATCH + B0 + row];
            loss_local += fmaxf(l, 0.0f) + log1pf(__expf(-fabsf(l))) - g * l;
        }
    }

    // ---- CTA reduction + single atomicAdd into d_out
    __shared__ float red[NTHREADS];
    red[tid] = loss_local;
    __syncthreads();
    for (int sft = NTHREADS / 2; sft > 0; sft >>= 1) {
        if (tid < sft) red[tid] += red[tid + sft];
        __syncthreads();
    }
    if (tid == 0 && cu == 0) atomicAdd(out, red[0]);
}

extern "C" void kernel_launch(void* const* d_in, const int* in_sizes, int n_in,
                              void* d_out, int out_size) {
    const float* x     = (const float*)d_in[0];
    const float* gt    = (const float*)d_in[1];
    const float* W_ih  = (const float*)d_in[2];
    const float* W_hh  = (const float*)d_in[3];
    const float* b_ih  = (const float*)d_in[4];
    const float* b_hh  = (const float*)d_in[5];
    const float* W_dec = (const float*)d_in[6];
    const float* b_dec = (const float*)d_in[7];
    float* out = (float*)d_out;

    cudaFuncSetAttribute(gru_main_kernel,
                         cudaFuncAttributeMaxDynamicSharedMemorySize, SMEM_BYTES);

    gru_init_kernel<<<64, 256>>>(out);
    gru_main_kernel<<<GRID_X, NTHREADS, SMEM_BYTES>>>(
        x, gt, W_ih, W_hh, b_ih, b_hh, W_dec, b_dec, out);
}

// round 3
// speedup vs baseline: 1.0073x; 1.0073x over previous
#include <cuda_runtime.h>

// ---------------------------------------------------------------------------
// GRU recurrence (511 steps) + BCE loss. Persistent kernel, 128 CTAs.
// Round-3: fma.rn.f32x2 packed math, pre-duplicated W in smem, transposed A
// staging (conflict-free), per-batch-group (16-CTA) software barriers.
//
// CTA tile: 32 batch rows x 16 hidden units (48 gate rows), K = 384 = [h|x].
// Thread: 4 rows x 3 gates x K-half. 256 threads, 8 warps.
// ---------------------------------------------------------------------------

#define T_SEQ   512
#define BATCH   256
#define IN_DIM  128
#define HID     256
#define STEPS   (T_SEQ - 1)     // 511

#define NCTA     128
#define NTHREADS 256
#define BM       32
#define NU       16
#define RGSTR    1540           // floats: A row-group stride (384*4 + 4) -> bank-spread
#define RWSTR    386            // u64:   Wdup row stride -> bank-spread

// smem layout (bytes)
#define OFF_A   0
#define SZ_A    (8 * RGSTR * 4)         // 49280: A as [rowgrp][k][j=0..3]
#define OFF_W   (OFF_A + SZ_A)          // 49280
#define SZ_W    (48 * RWSTR * 8)        // 148224: W duplicated (w,w) per element
#define OFF_SC  (OFF_W + SZ_W)          // 197504: reduction scratch
#define SZ_SC   (128 * 8 * 8)           // 8192
#define OFF_B   (OFF_SC + SZ_SC)        // 205696: biases (64 floats)
#define SZ_B    256
#define OFF_WD  (OFF_B + SZ_B)          // 205952: W_dec (256 floats)
#define SZ_WD   1024
#define SMEM_BYTES (OFF_WD + SZ_WD)     // 206976

typedef unsigned long long u64;

__device__ float    g_h[2][BATCH * HID];
__device__ unsigned g_arr[8 * 32];      // one counter per batch-group, 128B apart
__device__ unsigned g_rel[8 * 32];

__global__ void gru_init_kernel(float* out) {
    int i = blockIdx.x * blockDim.x + threadIdx.x;
    if (i == 0) out[0] = 0.0f;
    if (i < 8 * 32) { g_arr[i] = 0u; g_rel[i] = 0u; }
    for (int j = i; j < BATCH * HID; j += gridDim.x * blockDim.x)
        g_h[0][j] = 0.0f;
}

__device__ __forceinline__ u64 ffma2(u64 a, u64 b, u64 c) {
    u64 d;
    asm("fma.rn.f32x2 %0, %1, %2, %3;" : "=l"(d) : "l"(a), "l"(b), "l"(c));
    return d;
}
__device__ __forceinline__ float2 up2(u64 u) {
    float2 f;
    f.x = __uint_as_float((unsigned)u);
    f.y = __uint_as_float((unsigned)(u >> 32));
    return f;
}
__device__ __forceinline__ float sigf(float v) { return 1.0f / (1.0f + __expf(-v)); }

__device__ __forceinline__ void group_arrive(int cb, unsigned gen) {
    __threadfence();
    unsigned a = atomicAdd(&g_arr[cb * 32], 1u) + 1u;
    if (a == gen * 16u) atomicExch(&g_rel[cb * 32], gen);
}
__device__ __forceinline__ void group_wait(int cb, unsigned gen) {
    volatile unsigned* rel = &g_rel[cb * 32];
    while (*rel < gen) __nanosleep(32);
    __threadfence();            // fence.gpu -> CCTL.IVALL: invalidates stale L1
}

__global__ __launch_bounds__(NTHREADS)
void gru_main_kernel(const float* __restrict__ x,
                     const float* __restrict__ gt,
                     const float* __restrict__ W_ih,
                     const float* __restrict__ W_hh,
                     const float* __restrict__ b_ih,
                     const float* __restrict__ b_hh,
                     const float* __restrict__ W_dec,
                     const float* __restrict__ b_dec,
                     float* __restrict__ out)
{
    extern __shared__ char smem_raw[];
    float* sA  = (float*)(smem_raw + OFF_A);
    u64*   sW  = (u64*)  (smem_raw + OFF_W);
    u64*   sc  = (u64*)  (smem_raw + OFF_SC);
    float* sb  = (float*)(smem_raw + OFF_B);
    float* sWd = (float*)(smem_raw + OFF_WD);

    const int tid  = threadIdx.x;
    const int cb   = blockIdx.x & 7;        // batch group (32 rows)
    const int cu   = blockIdx.x >> 3;       // unit group (16 units)
    const int B0   = cb * BM;
    const int U0   = cu * NU;

    const int lane = tid & 31;
    const int rg   = lane & 7;              // row group (4 rows)
    const int u_lo = lane >> 3;             // 0..3
    const int w    = tid >> 5;
    const int kh   = w & 1;                 // K-half
    const int u_hi = w >> 1;                // 0..3
    const int u    = u_hi * 4 + u_lo;       // hidden unit 0..15

    // ---- build duplicated weight tile: sW[c*RWSTR + k] = (w,w), c = gate*16+uu
    for (int idx = tid; idx < 48 * 384; idx += NTHREADS) {
        int c = idx / 384;
        int k = idx - c * 384;
        int g = c >> 4, uu = c & 15;
        int wrow = g * HID + U0 + uu;
        float wv = (k < HID) ? W_hh[wrow * HID + k]
                             : W_ih[wrow * IN_DIM + (k - HID)];
        unsigned bits = __float_as_uint(wv);
        sW[c * RWSTR + k] = ((u64)bits << 32) | (u64)bits;
    }
    if (tid < 16) {
        sb[tid]      = b_ih[U0 + tid]           + b_hh[U0 + tid];
        sb[16 + tid] = b_ih[HID + U0 + tid]     + b_hh[HID + U0 + tid];
        sb[32 + tid] = b_ih[2 * HID + U0 + tid];
        sb[48 + tid] = b_hh[2 * HID + U0 + tid];
    }
    sWd[tid] = W_dec[tid];
    __syncthreads();

    const float bdec = b_dec[0];
    float loss_local = 0.0f;
    int p = 0;

    // per-thread smem pointers for the GEMM
    const ulonglong2* Ap = (const ulonglong2*)(sA + rg * RGSTR);      // Ap[k]: 4 rows at k
    const ulonglong2* Wr = (const ulonglong2*)(sW + (u)        * RWSTR);
    const ulonglong2* Wz = (const ulonglong2*)(sW + (16 + u)   * RWSTR);
    const ulonglong2* Wn = (const ulonglong2*)(sW + (32 + u)   * RWSTR);
    const int sidx = (u_hi * 32 + lane) * 8;

    for (int t = 0; t < STEPS; ++t) {
        // ---- stage x-part (k4 = 64..95), no dependency on h: overlap barrier
        {
            int rg_s = tid & 7;
            int k4   = 64 + (tid >> 3);
            const float* base = x + ((size_t)t * BATCH + B0 + rg_s * 4) * IN_DIM
                                  + (k4 - 64) * 4;
            float4 v0 = *(const float4*)(base);
            float4 v1 = *(const float4*)(base + IN_DIM);
            float4 v2 = *(const float4*)(base + 2 * IN_DIM);
            float4 v3 = *(const float4*)(base + 3 * IN_DIM);
            float4* dst = (float4*)(sA + rg_s * RGSTR + k4 * 16);
            dst[0] = make_float4(v0.x, v1.x, v2.x, v3.x);
            dst[1] = make_float4(v0.y, v1.y, v2.y, v3.y);
            dst[2] = make_float4(v0.z, v1.z, v2.z, v3.z);
            dst[3] = make_float4(v0.w, v1.w, v2.w, v3.w);
        }

        // ---- wait for h(t) from the 15 sibling CTAs
        if (t > 0) {
            __syncthreads();
            if (tid == 0) group_wait(cb, (unsigned)t);
            __syncthreads();
        }

        // ---- stage h-part (k4 = 0..63) transposed
        #pragma unroll
        for (int q = 0; q < 2; ++q) {
            int s    = tid + q * 256;
            int rg_s = s & 7;
            int k4   = s >> 3;
            const float* base = g_h[p] + (B0 + rg_s * 4) * HID + k4 * 4;
            float4 v0 = *(const float4*)(base);
            float4 v1 = *(const float4*)(base + HID);
            float4 v2 = *(const float4*)(base + 2 * HID);
            float4 v3 = *(const float4*)(base + 3 * HID);
            float4* dst = (float4*)(sA + rg_s * RGSTR + k4 * 16);
            dst[0] = make_float4(v0.x, v1.x, v2.x, v3.x);
            dst[1] = make_float4(v0.y, v1.y, v2.y, v3.y);
            dst[2] = make_float4(v0.z, v1.z, v2.z, v3.z);
            dst[3] = make_float4(v0.w, v1.w, v2.w, v3.w);
        }
        __syncthreads();

        // ---- deferred loss for h(t) (staged h-part), gt[t]; cu==0 only
        if (cu == 0 && t > 0) {
            int row = tid >> 3, seg = tid & 7;
            const float* ap = sA + (row >> 2) * RGSTR + (row & 3);
            float s = 0.0f;
            #pragma unroll
            for (int k = 0; k < 32; ++k) {
                int kk = seg * 32 + k;
                s += ap[kk * 4] * sWd[kk];
            }
            s += __shfl_down_sync(0xffffffffu, s, 4);
            s += __shfl_down_sync(0xffffffffu, s, 2);
            s += __shfl_down_sync(0xffffffffu, s, 1);
            if (seg == 0) {
                float l = s + bdec;
                float g = gt[t * BATCH + B0 + row];
                loss_local += fmaxf(l, 0.0f) + log1pf(__expf(-fabsf(l))) - g * l;
            }
        }

        // ---- GEMM: 4 rows (2 packed pairs) x 3 gates, K-half, f32x2
        u64 r0 = 0, r1 = 0, z0 = 0, z1 = 0, nh0 = 0, nh1 = 0, ni0 = 0, ni1 = 0;

        #define STEP_K2(K2, N0, N1) {                                   \
            ulonglong2 a0 = Ap[2 * (K2)];                               \
            ulonglong2 a1 = Ap[2 * (K2) + 1];                           \
            ulonglong2 wr = Wr[K2], wz = Wz[K2], wn = Wn[K2];           \
            r0 = ffma2(a0.x, wr.x, r0);  r1 = ffma2(a0.y, wr.x, r1);    \
            z0 = ffma2(a0.x, wz.x, z0);  z1 = ffma2(a0.y, wz.x, z1);    \
            N0 = ffma2(a0.x, wn.x, N0);  N1 = ffma2(a0.y, wn.x, N1);    \
            r0 = ffma2(a1.x, wr.y, r0);  r1 = ffma2(a1.y, wr.y, r1);    \
            z0 = ffma2(a1.x, wz.y, z0);  z1 = ffma2(a1.y, wz.y, z1);    \
            N0 = ffma2(a1.x, wn.y, N0);  N1 = ffma2(a1.y, wn.y, N1); }

        if (kh == 0) {
            #pragma unroll 8
            for (int k2 = 0; k2 < 96; ++k2) STEP_K2(k2, nh0, nh1)
        } else {
            #pragma unroll 8
            for (int k2 = 96; k2 < 128; ++k2) STEP_K2(k2, nh0, nh1)
            #pragma unroll 8
            for (int k2 = 128; k2 < 192; ++k2) STEP_K2(k2, ni0, ni1)
        }
        #undef STEP_K2

        // ---- cross-K-half reduction + epilogue (kh==0 threads)
        if (kh == 1) {
            sc[sidx]     = r0;  sc[sidx + 1] = r1;
            sc[sidx + 2] = z0;  sc[sidx + 3] = z1;
            sc[sidx + 4] = nh0; sc[sidx + 5] = nh1;
            sc[sidx + 6] = ni0; sc[sidx + 7] = ni1;
        }
        __syncthreads();
        if (kh == 0) {
            float2 pr0 = up2(sc[sidx]),     pr1 = up2(sc[sidx + 1]);
            float2 pz0 = up2(sc[sidx + 2]), pz1 = up2(sc[sidx + 3]);
            float2 ph0 = up2(sc[sidx + 4]), ph1 = up2(sc[sidx + 5]);
            float2 pi0 = up2(sc[sidx + 6]), pi1 = up2(sc[sidx + 7]);
            float2 cr0 = up2(r0), cr1 = up2(r1);
            float2 cz0 = up2(z0), cz1 = up2(z1);
            float2 ch0 = up2(nh0), ch1 = up2(nh1);
            float2 ci0 = up2(ni0), ci1 = up2(ni1);

            float rr[4] = {cr0.x + pr0.x, cr0.y + pr0.y, cr1.x + pr1.x, cr1.y + pr1.y};
            float zz[4] = {cz0.x + pz0.x, cz0.y + pz0.y, cz1.x + pz1.x, cz1.y + pz1.y};
            float hh[4] = {ch0.x + ph0.x, ch0.y + ph0.y, ch1.x + ph1.x, ch1.y + ph1.y};
            float xi[4] = {ci0.x + pi0.x, ci0.y + pi0.y, ci1.x + pi1.x, ci1.y + pi1.y};

            float br = sb[u], bz = sb[16 + u], bni = sb[32 + u], bnh = sb[48 + u];
            float* hdst = g_h[p ^ 1];
            #pragma unroll
            for (int j = 0; j < 4; ++j) {
                float rv = sigf(rr[j] + br);
                float zv = sigf(zz[j] + bz);
                float nv = tanhf(xi[j] + bni + rv * (hh[j] + bnh));
                float hp = sA[rg * RGSTR + (U0 + u) * 4 + j];
                float hn = nv + zv * (hp - nv);
                hdst[(B0 + rg * 4 + j) * HID + U0 + u] = hn;
            }
        }
        __syncthreads();
        if (tid == 0) group_arrive(cb, (unsigned)(t + 1));
        p ^= 1;
    }

    // ---- final-step loss: needs all columns of h(511)
    if (tid == 0) group_wait(cb, (unsigned)STEPS);
    __syncthreads();
    if (cu == 0) {
        int row = tid >> 3, seg = tid & 7;
        const float4* hr = (const float4*)(g_h[p] + (B0 + row) * HID) + seg * 8;
        const float4* wd = (const float4*)sWd + seg * 8;
        float s = 0.0f;
        #pragma unroll
        for (int j = 0; j < 8; ++j) {
            float4 a = hr[j];
            float4 wv = wd[j];
            s += a.x * wv.x + a.y * wv.y + a.z * wv.z + a.w * wv.w;
        }
        s += __shfl_down_sync(0xffffffffu, s, 4);
        s += __shfl_down_sync(0xffffffffu, s, 2);
        s += __shfl_down_sync(0xffffffffu, s, 1);
        if (seg == 0) {
            float l = s + bdec;
            float g = gt[(size_t)STEPS * BATCH + B0 + row];
            loss_local += fmaxf(l, 0.0f) + log1pf(__expf(-fabsf(l))) - g * l;
        }
    }

    // ---- CTA reduce + one atomicAdd per cu==0 CTA
    float* red = (float*)sc;
    red[tid] = loss_local;
    __syncthreads();
    for (int sft = NTHREADS / 2; sft > 0; sft >>= 1) {
        if (tid < sft) red[tid] += red[tid + sft];
        __syncthreads();
    }
    if (tid == 0 && cu == 0) atomicAdd(out, red[0]);
}

extern "C" void kernel_launch(void* const* d_in, const int* in_sizes, int n_in,
                              void* d_out, int out_size) {
    const float* x     = (const float*)d_in[0];
    const float* gt    = (const float*)d_in[1];
    const float* W_ih  = (const float*)d_in[2];
    const float* W_hh  = (const float*)d_in[3];
    const float* b_ih  = (const float*)d_in[4];
    const float* b_hh  = (const float*)d_in[5];
    const float* W_dec = (const float*)d_in[6];
    const float* b_dec = (const float*)d_in[7];
    float* out = (float*)d_out;

    cudaFuncSetAttribute(gru_main_kernel,
                         cudaFuncAttributeMaxDynamicSharedMemorySize, SMEM_BYTES);

    gru_init_kernel<<<64, 256>>>(out);
    gru_main_kernel<<<NCTA, NTHREADS, SMEM_BYTES>>>(
        x, gt, W_ih, W_hh, b_ih, b_hh, W_dec, b_dec, out);
}

// round 4
// speedup vs baseline: 1.0277x; 1.0203x over previous
#include <cuda_runtime.h>

// ---------------------------------------------------------------------------
// GRU recurrence (511 steps) + BCE loss. Persistent kernel, 128 CTAs.
// Round-3: fma.rn.f32x2 packed math, pre-duplicated W in smem, transposed A
// staging (conflict-free), per-batch-group (16-CTA) software barriers.
//
// CTA tile: 32 batch rows x 16 hidden units (48 gate rows), K = 384 = [h|x].
// Thread: 4 rows x 3 gates x K-half. 256 threads, 8 warps.
// ---------------------------------------------------------------------------

#define T_SEQ   512
#define BATCH   256
#define IN_DIM  128
#define HID     256
#define STEPS   (T_SEQ - 1)     // 511

#define NCTA     128
#define NTHREADS 256
#define BM       32
#define NU       16
#define RGSTR    1540           // floats: A row-group stride (384*4 + 4) -> bank-spread
#define RWSTR    386            // u64:   Wdup row stride -> bank-spread

// smem layout (bytes)
#define OFF_A   0
#define SZ_A    (8 * RGSTR * 4)         // 49280: A as [rowgrp][k][j=0..3]
#define OFF_W   (OFF_A + SZ_A)          // 49280
#define SZ_W    (48 * RWSTR * 8)        // 148224: W duplicated (w,w) per element
#define OFF_SC  (OFF_W + SZ_W)          // 197504: reduction scratch
#define SZ_SC   (128 * 8 * 8)           // 8192
#define OFF_B   (OFF_SC + SZ_SC)        // 205696: biases (64 floats)
#define SZ_B    256
#define OFF_WD  (OFF_B + SZ_B)          // 205952: W_dec (256 floats)
#define SZ_WD   1024
#define SMEM_BYTES (OFF_WD + SZ_WD)     // 206976

typedef unsigned long long u64;

__device__ float    g_h[2][BATCH * HID];
__device__ unsigned g_arr[8 * 32];      // one counter per batch-group, 128B apart
__device__ unsigned g_rel[8 * 32];

__global__ void gru_init_kernel(float* out) {
    int i = blockIdx.x * blockDim.x + threadIdx.x;
    if (i == 0) out[0] = 0.0f;
    if (i < 8 * 32) { g_arr[i] = 0u; g_rel[i] = 0u; }
    for (int j = i; j < BATCH * HID; j += gridDim.x * blockDim.x)
        g_h[0][j] = 0.0f;
}

__device__ __forceinline__ u64 ffma2(u64 a, u64 b, u64 c) {
    u64 d;
    asm("fma.rn.f32x2 %0, %1, %2, %3;" : "=l"(d) : "l"(a), "l"(b), "l"(c));
    return d;
}
__device__ __forceinline__ float2 up2(u64 u) {
    float2 f;
    f.x = __uint_as_float((unsigned)u);
    f.y = __uint_as_float((unsigned)(u >> 32));
    return f;
}
__device__ __forceinline__ float sigf(float v) { return 1.0f / (1.0f + __expf(-v)); }

__device__ __forceinline__ void group_arrive(int cb, unsigned gen) {
    __threadfence();
    unsigned a = atomicAdd(&g_arr[cb * 32], 1u) + 1u;
    if (a == gen * 16u) atomicExch(&g_rel[cb * 32], gen);
}
__device__ __forceinline__ void group_wait(int cb, unsigned gen) {
    volatile unsigned* rel = &g_rel[cb * 32];
    while (*rel < gen) __nanosleep(32);
    __threadfence();            // fence.gpu -> CCTL.IVALL: invalidates stale L1
}

__global__ __launch_bounds__(NTHREADS)
void gru_main_kernel(const float* __restrict__ x,
                     const float* __restrict__ gt,
                     const float* __restrict__ W_ih,
                     const float* __restrict__ W_hh,
                     const float* __restrict__ b_ih,
                     const float* __restrict__ b_hh,
                     const float* __restrict__ W_dec,
                     const float* __restrict__ b_dec,
                     float* __restrict__ out)
{
    extern __shared__ char smem_raw[];
    float* sA  = (float*)(smem_raw + OFF_A);
    u64*   sW  = (u64*)  (smem_raw + OFF_W);
    u64*   sc  = (u64*)  (smem_raw + OFF_SC);
    float* sb  = (float*)(smem_raw + OFF_B);
    float* sWd = (float*)(smem_raw + OFF_WD);

    const int tid  = threadIdx.x;
    const int cb   = blockIdx.x & 7;        // batch group (32 rows)
    const int cu   = blockIdx.x >> 3;       // unit group (16 units)
    const int B0   = cb * BM;
    const int U0   = cu * NU;

    const int lane = tid & 31;
    const int rg   = lane & 7;              // row group (4 rows)
    const int u_lo = lane >> 3;             // 0..3
    const int w    = tid >> 5;
    const int kh   = w & 1;                 // K-half
    const int u_hi = w >> 1;                // 0..3
    const int u    = u_hi * 4 + u_lo;       // hidden unit 0..15

    // ---- build duplicated weight tile: sW[c*RWSTR + k] = (w,w), c = gate*16+uu
    for (int idx = tid; idx < 48 * 384; idx += NTHREADS) {
        int c = idx / 384;
        int k = idx - c * 384;
        int g = c >> 4, uu = c & 15;
        int wrow = g * HID + U0 + uu;
        float wv = (k < HID) ? W_hh[wrow * HID + k]
                             : W_ih[wrow * IN_DIM + (k - HID)];
        unsigned bits = __float_as_uint(wv);
        sW[c * RWSTR + k] = ((u64)bits << 32) | (u64)bits;
    }
    if (tid < 16) {
        sb[tid]      = b_ih[U0 + tid]           + b_hh[U0 + tid];
        sb[16 + tid] = b_ih[HID + U0 + tid]     + b_hh[HID + U0 + tid];
        sb[32 + tid] = b_ih[2 * HID + U0 + tid];
        sb[48 + tid] = b_hh[2 * HID + U0 + tid];
    }
    sWd[tid] = W_dec[tid];
    __syncthreads();

    const float bdec = b_dec[0];
    float loss_local = 0.0f;
    int p = 0;

    // per-thread smem pointers for the GEMM
    const ulonglong2* Ap = (const ulonglong2*)(sA + rg * RGSTR);      // Ap[k]: 4 rows at k
    const ulonglong2* Wr = (const ulonglong2*)(sW + (u)        * RWSTR);
    const ulonglong2* Wz = (const ulonglong2*)(sW + (16 + u)   * RWSTR);
    const ulonglong2* Wn = (const ulonglong2*)(sW + (32 + u)   * RWSTR);
    const int sidx = (u_hi * 32 + lane) * 8;

    for (int t = 0; t < STEPS; ++t) {
        // ---- stage x-part (k4 = 64..95), no dependency on h: overlap barrier
        {
            int rg_s = tid & 7;
            int k4   = 64 + (tid >> 3);
            const float* base = x + ((size_t)t * BATCH + B0 + rg_s * 4) * IN_DIM
                                  + (k4 - 64) * 4;
            float4 v0 = *(const float4*)(base);
            float4 v1 = *(const float4*)(base + IN_DIM);
            float4 v2 = *(const float4*)(base + 2 * IN_DIM);
            float4 v3 = *(const float4*)(base + 3 * IN_DIM);
            float4* dst = (float4*)(sA + rg_s * RGSTR + k4 * 16);
            dst[0] = make_float4(v0.x, v1.x, v2.x, v3.x);
            dst[1] = make_float4(v0.y, v1.y, v2.y, v3.y);
            dst[2] = make_float4(v0.z, v1.z, v2.z, v3.z);
            dst[3] = make_float4(v0.w, v1.w, v2.w, v3.w);
        }

        // ---- wait for h(t) from the 15 sibling CTAs
        if (t > 0) {
            __syncthreads();
            if (tid == 0) group_wait(cb, (unsigned)t);
            __syncthreads();
        }

        // ---- stage h-part (k4 = 0..63) transposed
        #pragma unroll
        for (int q = 0; q < 2; ++q) {
            int s    = tid + q * 256;
            int rg_s = s & 7;
            int k4   = s >> 3;
            const float* base = g_h[p] + (B0 + rg_s * 4) * HID + k4 * 4;
            float4 v0 = *(const float4*)(base);
            float4 v1 = *(const float4*)(base + HID);
            float4 v2 = *(const float4*)(base + 2 * HID);
            float4 v3 = *(const float4*)(base + 3 * HID);
            float4* dst = (float4*)(sA + rg_s * RGSTR + k4 * 16);
            dst[0] = make_float4(v0.x, v1.x, v2.x, v3.x);
            dst[1] = make_float4(v0.y, v1.y, v2.y, v3.y);
            dst[2] = make_float4(v0.z, v1.z, v2.z, v3.z);
            dst[3] = make_float4(v0.w, v1.w, v2.w, v3.w);
        }
        __syncthreads();

        // ---- deferred loss for h(t) (staged h-part), gt[t]; cu==0 only
        if (cu == 0 && t > 0) {
            int row = tid >> 3, seg = tid & 7;
            const float* ap = sA + (row >> 2) * RGSTR + (row & 3);
            float s = 0.0f;
            #pragma unroll
            for (int k = 0; k < 32; ++k) {
                int kk = seg * 32 + k;
                s += ap[kk * 4] * sWd[kk];
            }
            s += __shfl_down_sync(0xffffffffu, s, 4);
            s += __shfl_down_sync(0xffffffffu, s, 2);
            s += __shfl_down_sync(0xffffffffu, s, 1);
            if (seg == 0) {
                float l = s + bdec;
                float g = gt[t * BATCH + B0 + row];
                loss_local += fmaxf(l, 0.0f) + log1pf(__expf(-fabsf(l))) - g * l;
            }
        }

        // ---- GEMM: 4 rows (2 packed pairs) x 3 gates, K-half, f32x2
        u64 r0 = 0, r1 = 0, z0 = 0, z1 = 0, nh0 = 0, nh1 = 0, ni0 = 0, ni1 = 0;

        #define STEP_K2(K2, N0, N1) {                                   \
            ulonglong2 a0 = Ap[2 * (K2)];                               \
            ulonglong2 a1 = Ap[2 * (K2) + 1];                           \
            ulonglong2 wr = Wr[K2], wz = Wz[K2], wn = Wn[K2];           \
            r0 = ffma2(a0.x, wr.x, r0);  r1 = ffma2(a0.y, wr.x, r1);    \
            z0 = ffma2(a0.x, wz.x, z0);  z1 = ffma2(a0.y, wz.x, z1);    \
            N0 = ffma2(a0.x, wn.x, N0);  N1 = ffma2(a0.y, wn.x, N1);    \
            r0 = ffma2(a1.x, wr.y, r0);  r1 = ffma2(a1.y, wr.y, r1);    \
            z0 = ffma2(a1.x, wz.y, z0);  z1 = ffma2(a1.y, wz.y, z1);    \
            N0 = ffma2(a1.x, wn.y, N0);  N1 = ffma2(a1.y, wn.y, N1); }

        if (kh == 0) {
            #pragma unroll 8
            for (int k2 = 0; k2 < 96; ++k2) STEP_K2(k2, nh0, nh1)
        } else {
            #pragma unroll 8
            for (int k2 = 96; k2 < 128; ++k2) STEP_K2(k2, nh0, nh1)
            #pragma unroll 8
            for (int k2 = 128; k2 < 192; ++k2) STEP_K2(k2, ni0, ni1)
        }
        #undef STEP_K2

        // ---- cross-K-half reduction + epilogue (kh==0 threads)
        if (kh == 1) {
            sc[sidx]     = r0;  sc[sidx + 1] = r1;
            sc[sidx + 2] = z0;  sc[sidx + 3] = z1;
            sc[sidx + 4] = nh0; sc[sidx + 5] = nh1;
            sc[sidx + 6] = ni0; sc[sidx + 7] = ni1;
        }
        __syncthreads();
        if (kh == 0) {
            float2 pr0 = up2(sc[sidx]),     pr1 = up2(sc[sidx + 1]);
            float2 pz0 = up2(sc[sidx + 2]), pz1 = up2(sc[sidx + 3]);
            float2 ph0 = up2(sc[sidx + 4]), ph1 = up2(sc[sidx + 5]);
            float2 pi0 = up2(sc[sidx + 6]), pi1 = up2(sc[sidx + 7]);
            float2 cr0 = up2(r0), cr1 = up2(r1);
            float2 cz0 = up2(z0), cz1 = up2(z1);
            float2 ch0 = up2(nh0), ch1 = up2(nh1);
            float2 ci0 = up2(ni0), ci1 = up2(ni1);

            float rr[4] = {cr0.x + pr0.x, cr0.y + pr0.y, cr1.x + pr1.x, cr1.y + pr1.y};
            float zz[4] = {cz0.x + pz0.x, cz0.y + pz0.y, cz1.x + pz1.x, cz1.y + pz1.y};
            float hh[4] = {ch0.x + ph0.x, ch0.y + ph0.y, ch1.x + ph1.x, ch1.y + ph1.y};
            float xi[4] = {ci0.x + pi0.x, ci0.y + pi0.y, ci1.x + pi1.x, ci1.y + pi1.y};

            float br = sb[u], bz = sb[16 + u], bni = sb[32 + u], bnh = sb[48 + u];
            float* hdst = g_h[p ^ 1];
            #pragma unroll
            for (int j = 0; j < 4; ++j) {
                float rv = sigf(rr[j] + br);
                float zv = sigf(zz[j] + bz);
                float nv = tanhf(xi[j] + bni + rv * (hh[j] + bnh));
                float hp = sA[rg * RGSTR + (U0 + u) * 4 + j];
                float hn = nv + zv * (hp - nv);
                hdst[(B0 + rg * 4 + j) * HID + U0 + u] = hn;
            }
        }
        __syncthreads();
        if (tid == 0) group_arrive(cb, (unsigned)(t + 1));
        p ^= 1;
    }

    // ---- final-step loss: needs all columns of h(511)
    if (tid == 0) group_wait(cb, (unsigned)STEPS);
    __syncthreads();
    if (cu == 0) {
        int row = tid >> 3, seg = tid & 7;
        const float4* hr = (const float4*)(g_h[p] + (B0 + row) * HID) + seg * 8;
        const float4* wd = (const float4*)sWd + seg * 8;
        float s = 0.0f;
        #pragma unroll
        for (int j = 0; j < 8; ++j) {
            float4 a = hr[j];
            float4 wv = wd[j];
            s += a.x * wv.x + a.y * wv.y + a.z * wv.z + a.w * wv.w;
        }
        s += __shfl_down_sync(0xffffffffu, s, 4);
        s += __shfl_down_sync(0xffffffffu, s, 2);
        s += __shfl_down_sync(0xffffffffu, s, 1);
        if (seg == 0) {
            float l = s + bdec;
            float g = gt[(size_t)STEPS * BATCH + B0 + row];
            loss_local += fmaxf(l, 0.0f) + log1pf(__expf(-fabsf(l))) - g * l;
        }
    }

    // ---- CTA reduce + one atomicAdd per cu==0 CTA
    float* red = (float*)sc;
    red[tid] = loss_local;
    __syncthreads();
    for (int sft = NTHREADS / 2; sft > 0; sft >>= 1) {
        if (tid < sft) red[tid] += red[tid + sft];
        __syncthreads();
    }
    if (tid == 0 && cu == 0) atomicAdd(out, red[0]);
}

extern "C" void kernel_launch(void* const* d_in, const int* in_sizes, int n_in,
                              void* d_out, int out_size) {
    const float* x     = (const float*)d_in[0];
    const float* gt    = (const float*)d_in[1];
    const float* W_ih  = (const float*)d_in[2];
    const float* W_hh  = (const float*)d_in[3];
    const float* b_ih  = (const float*)d_in[4];
    const float* b_hh  = (const float*)d_in[5];
    const float* W_dec = (const float*)d_in[6];
    const float* b_dec = (const float*)d_in[7];
    float* out = (float*)d_out;

    cudaFuncSetAttribute(gru_main_kernel,
                         cudaFuncAttributeMaxDynamicSharedMemorySize, SMEM_BYTES);

    gru_init_kernel<<<64, 256>>>(out);
    gru_main_kernel<<<NCTA, NTHREADS, SMEM_BYTES>>>(
        x, gt, W_ih, W_hh, b_ih, b_hh, W_dec, b_dec, out);
}

// round 5
// speedup vs baseline: 1.4307x; 1.3921x over previous
#include <cuda_runtime.h>

// ---------------------------------------------------------------------------
// GRU recurrence (511 steps) + BCE loss. Persistent kernel, 256 CTAs
// (16 batch-groups x 16 unit-groups), 2 CTAs/SM, 256 threads each.
// CTA tile: 16 batch rows x 16 hidden units (48 gate rows), K = 384 = [h|x].
// Thread: 2 rows x 1 unit (3 gates) x K-half, k-packed fma.rn.f32x2.
// ---------------------------------------------------------------------------

#define BATCH   256
#define IN_DIM  128
#define HID     256
#define STEPS   511

#define NCTA     256
#define NTHREADS 256
#define BM       16             // batch rows per group/CTA
#define NU       16             // hidden units per CTA
#define WSTR     388            // W row stride (floats): 1552B % 128 = 16
#define PSTR     772            // A row-pair stride (floats): 3088B % 128 = 16

// smem layout (float offsets)
#define OFF_W   0                           // 48 x WSTR
#define OFF_A   (48 * WSTR)                 // 18624: 8 pairs x PSTR
#define OFF_SC  (OFF_A + 8 * PSTR)          // 24800: 128 slots x 8 u64 (2048 f)
#define OFF_SB  (OFF_SC + 2048)             // 26848: biases (64)
#define OFF_WD  (OFF_SB + 64)               // 26912: W_dec (256)
#define SMEM_FLOATS (OFF_WD + 256)          // 27168
#define SMEM_BYTES  (SMEM_FLOATS * 4)       // 108672

typedef unsigned long long u64;

__device__ float    g_h[2][BATCH * HID];
__device__ unsigned g_arr[16 * 32];         // one counter per batch group

__global__ void gru_init_kernel(float* out) {
    int i = blockIdx.x * blockDim.x + threadIdx.x;
    if (i == 0) out[0] = 0.0f;
    if (i < 16 * 32) g_arr[i] = 0u;
    for (int j = i; j < BATCH * HID; j += gridDim.x * blockDim.x)
        g_h[0][j] = 0.0f;
}

__device__ __forceinline__ u64 ffma2(u64 a, u64 b, u64 c) {
    u64 d;
    asm("fma.rn.f32x2 %0, %1, %2, %3;" : "=l"(d) : "l"(a), "l"(b), "l"(c));
    return d;
}
__device__ __forceinline__ float up_sum(u64 u) {
    return __uint_as_float((unsigned)u) + __uint_as_float((unsigned)(u >> 32));
}
__device__ __forceinline__ float sigf(float v) { return 1.0f / (1.0f + __expf(-v)); }
__device__ __forceinline__ float tanhfast(float v) { return 2.0f * sigf(2.0f * v) - 1.0f; }

__device__ __forceinline__ unsigned ld_acq(const unsigned* p) {
    unsigned v;
    asm volatile("ld.acquire.gpu.global.u32 %0, [%1];" : "=r"(v) : "l"(p) : "memory");
    return v;
}

__global__ __launch_bounds__(NTHREADS, 2)
void gru_main_kernel(const float* __restrict__ x,
                     const float* __restrict__ gt,
                     const float* __restrict__ W_ih,
                     const float* __restrict__ W_hh,
                     const float* __restrict__ b_ih,
                     const float* __restrict__ b_hh,
                     const float* __restrict__ W_dec,
                     const float* __restrict__ b_dec,
                     float* __restrict__ out)
{
    extern __shared__ float smem[];
    float* sW  = smem + OFF_W;
    float* sA  = smem + OFF_A;
    u64*   sc  = (u64*)(smem + OFF_SC);
    float* sb  = smem + OFF_SB;
    float* sWd = smem + OFF_WD;

    const int tid  = threadIdx.x;
    const int cb   = blockIdx.x & 15;       // batch group (16 rows)
    const int cu   = blockIdx.x >> 4;       // unit group (16 units)
    const int B0   = cb * BM;
    const int U0   = cu * NU;

    const int lane = tid & 31;
    const int w    = tid >> 5;
    const int kh   = w & 1;                 // K-half: 0 -> k[0,192), 1 -> k[192,384)
    const int u_hi = w >> 1;                // 0..3
    const int rp   = lane & 7;              // row pair (rows 2rp, 2rp+1)
    const int u_lo = lane >> 3;             // 0..3
    const int u    = u_hi * 4 + u_lo;       // unit 0..15

    // ---- persistent W slice: 48 gate-rows x 384 k (k-major, no duplication)
    for (int idx = tid; idx < 48 * 384; idx += NTHREADS) {
        int c = idx / 384;
        int k = idx - c * 384;
        int g = c >> 4, uu = c & 15;
        int wrow = g * HID + U0 + uu;
        sW[c * WSTR + k] = (k < HID) ? W_hh[wrow * HID + k]
                                     : W_ih[wrow * IN_DIM + (k - HID)];
    }
    if (tid < 16) {
        sb[tid]      = b_ih[U0 + tid]           + b_hh[U0 + tid];        // r
        sb[16 + tid] = b_ih[HID + U0 + tid]     + b_hh[HID + U0 + tid];  // z
        sb[32 + tid] = b_ih[2 * HID + U0 + tid];                         // n (x)
        sb[48 + tid] = b_hh[2 * HID + U0 + tid];                         // n (h)
    }
    sWd[tid] = W_dec[tid];
    __syncthreads();

    const float bdec = b_dec[0];
    float loss_local = 0.0f;
    int p = 0;

    const ulonglong2* Ap = (const ulonglong2*)(sA + rp * PSTR);           // [2*k4 + j]
    const ulonglong2* Wr = (const ulonglong2*)(sW + (u)       * WSTR);
    const ulonglong2* Wz = (const ulonglong2*)(sW + (16 + u)  * WSTR);
    const ulonglong2* Wn = (const ulonglong2*)(sW + (32 + u)  * WSTR);
    u64* scp = sc + (u * 8 + rp) * 8;

    const unsigned* cnt = &g_arr[cb * 32];

    for (int t = 0; t < STEPS; ++t) {
        // ---- stage x(t) (k4 = 64..95): independent of h -> before the wait
        {
            int row  = tid >> 4;
            int c    = tid & 15;
            float* pairbase = sA + (row >> 1) * PSTR + (row & 1) * 4;
            const float* src = x + ((size_t)t * BATCH + B0 + row) * IN_DIM;
            #pragma unroll
            for (int q = 0; q < 2; ++q) {
                int col4 = c + 16 * q;
                float4 v = *(const float4*)(src + col4 * 4);
                *(float4*)(pairbase + (64 + col4) * 8) = v;
            }
        }

        // ---- wait for h(t) from sibling CTAs
        if (t > 0) {
            if (tid == 0) {
                unsigned target = (unsigned)t * 16u;
                while (ld_acq(cnt) < target) __nanosleep(20);
            }
            __syncthreads();
        }

        // ---- stage h(t) (k4 = 0..63), L1-bypassed loads
        {
            int row = tid >> 4;
            float* pairbase = sA + (row >> 1) * PSTR + (row & 1) * 4;
            const float4* src = (const float4*)(g_h[p] + (B0 + row) * HID);
            #pragma unroll
            for (int q = 0; q < 4; ++q) {
                int k4 = (tid & 15) + 16 * q;
                float4 v = __ldcg(src + k4);
                *(float4*)(pairbase + k4 * 8) = v;
            }
        }
        __syncthreads();

        // ---- loss for h(t) (this CTA handles global row B0+cu), gt[t]
        if (tid < 32 && t > 0) {
            const float* ap = sA + (cu >> 1) * PSTR + (cu & 1) * 4;
            float s = 0.0f;
            #pragma unroll
            for (int q = 0; q < 8; ++q) {
                int k = lane + 32 * q;
                s += ap[(k >> 2) * 8 + (k & 3)] * sWd[k];
            }
            #pragma unroll
            for (int sft = 16; sft > 0; sft >>= 1)
                s += __shfl_down_sync(0xffffffffu, s, sft);
            if (lane == 0) {
                float l = s + bdec;
                float g = gt[t * BATCH + B0 + cu];
                loss_local += fmaxf(l, 0.0f) + log1pf(__expf(-fabsf(l))) - g * l;
            }
        }

        // ---- GEMM: 2 rows x 3 gates x K-half, k-packed f32x2
        u64 r0 = 0, r1 = 0, z0 = 0, z1 = 0, nh0 = 0, nh1 = 0, ni0 = 0, ni1 = 0;

        #define STEP_K4(K4, N0, N1) {                                   \
            ulonglong2 a0 = Ap[2 * (K4)];                               \
            ulonglong2 a1 = Ap[2 * (K4) + 1];                           \
            ulonglong2 wr = Wr[K4], wz = Wz[K4], wn = Wn[K4];           \
            r0 = ffma2(a0.x, wr.x, r0);  r0 = ffma2(a0.y, wr.y, r0);    \
            r1 = ffma2(a1.x, wr.x, r1);  r1 = ffma2(a1.y, wr.y, r1);    \
            z0 = ffma2(a0.x, wz.x, z0);  z0 = ffma2(a0.y, wz.y, z0);    \
            z1 = ffma2(a1.x, wz.x, z1);  z1 = ffma2(a1.y, wz.y, z1);    \
            N0 = ffma2(a0.x, wn.x, N0);  N0 = ffma2(a0.y, wn.y, N0);    \
            N1 = ffma2(a1.x, wn.x, N1);  N1 = ffma2(a1.y, wn.y, N1); }

        if (kh == 0) {
            #pragma unroll 8
            for (int k4 = 0; k4 < 48; ++k4) STEP_K4(k4, nh0, nh1)
        } else {
            #pragma unroll 8
            for (int k4 = 48; k4 < 64; ++k4) STEP_K4(k4, nh0, nh1)
            #pragma unroll 8
            for (int k4 = 64; k4 < 96; ++k4) STEP_K4(k4, ni0, ni1)
        }
        #undef STEP_K4

        // ---- cross-half exchange
        if (kh == 1) {
            scp[0] = r0;  scp[1] = r1;  scp[2] = z0;  scp[3] = z1;
            scp[4] = nh0; scp[5] = nh1; scp[6] = ni0; scp[7] = ni1;
        }
        __syncthreads();

        // ---- epilogue (kh==0 warps): combine halves, gates, write h(t+1)
        if (kh == 0) {
            float rA = up_sum(r0)  + up_sum(scp[0]);
            float rB = up_sum(r1)  + up_sum(scp[1]);
            float zA = up_sum(z0)  + up_sum(scp[2]);
            float zB = up_sum(z1)  + up_sum(scp[3]);
            float hA = up_sum(nh0) + up_sum(scp[4]);
            float hB = up_sum(nh1) + up_sum(scp[5]);
            float iA = up_sum(ni0) + up_sum(scp[6]);
            float iB = up_sum(ni1) + up_sum(scp[7]);

            float br = sb[u], bz = sb[16 + u], bni = sb[32 + u], bnh = sb[48 + u];
            const float* pairbase = sA + rp * PSTR;
            int kidx = U0 + u;
            float hpA = pairbase[(kidx >> 2) * 8 + (kidx & 3)];
            float hpB = pairbase[(kidx >> 2) * 8 + 4 + (kidx & 3)];

            float rvA = sigf(rA + br), rvB = sigf(rB + br);
            float zvA = sigf(zA + bz), zvB = sigf(zB + bz);
            float nvA = tanhfast(iA + bni + rvA * (hA + bnh));
            float nvB = tanhfast(iB + bni + rvB * (hB + bnh));
            float hnA = nvA + zvA * (hpA - nvA);
            float hnB = nvB + zvB * (hpB - nvB);

            float* hdst = g_h[p ^ 1];
            hdst[(B0 + 2 * rp)     * HID + U0 + u] = hnA;
            hdst[(B0 + 2 * rp + 1) * HID + U0 + u] = hnB;
            __threadfence();
        }
        __syncthreads();
        if (tid == 0) atomicAdd((unsigned*)cnt, 1u);
        p ^= 1;
    }

    // ---- final-step loss for h(511), gt[511]
    if (tid == 0) {
        unsigned target = (unsigned)STEPS * 16u;
        while (ld_acq(cnt) < target) __nanosleep(20);
    }
    __syncthreads();
    if (tid < 32) {
        const float4* hr = (const float4*)(g_h[p] + (B0 + cu) * HID);
        float s = 0.0f;
        #pragma unroll
        for (int q = 0; q < 2; ++q) {
            int k4 = lane + 32 * q;
            float4 a = __ldcg(hr + k4);
            float4 wv = *(const float4*)(sWd + k4 * 4);
            s += a.x * wv.x + a.y * wv.y + a.z * wv.z + a.w * wv.w;
        }
        #pragma unroll
        for (int sft = 16; sft > 0; sft >>= 1)
            s += __shfl_down_sync(0xffffffffu, s, sft);
        if (lane == 0) {
            float l = s + bdec;
            float g = gt[(size_t)STEPS * BATCH + B0 + cu];
            loss_local += fmaxf(l, 0.0f) + log1pf(__expf(-fabsf(l))) - g * l;
        }
    }

    if (tid == 0) atomicAdd(out, loss_local);
}

extern "C" void kernel_launch(void* const* d_in, const int* in_sizes, int n_in,
                              void* d_out, int out_size) {
    const float* x     = (const float*)d_in[0];
    const float* gt    = (const float*)d_in[1];
    const float* W_ih  = (const float*)d_in[2];
    const float* W_hh  = (const float*)d_in[3];
    const float* b_ih  = (const float*)d_in[4];
    const float* b_hh  = (const float*)d_in[5];
    const float* W_dec = (const float*)d_in[6];
    const float* b_dec = (const float*)d_in[7];
    float* out = (float*)d_out;

    cudaFuncSetAttribute(gru_main_kernel,
                         cudaFuncAttributeMaxDynamicSharedMemorySize, SMEM_BYTES);

    gru_init_kernel<<<64, 256>>>(out);
    gru_main_kernel<<<NCTA, NTHREADS, SMEM_BYTES>>>(
        x, gt, W_ih, W_hh, b_ih, b_hh, W_dec, b_dec, out);
}

// round 6
// speedup vs baseline: 1.4315x; 1.0006x over previous
#include <cuda_runtime.h>

// ---------------------------------------------------------------------------
// GRU recurrence (511 steps) + BCE loss. Persistent kernel, 256 CTAs
// (16 batch-groups x 16 unit-groups), 2 CTAs/SM, 256 threads each.
// CTA tile: 16 batch rows x 16 hidden units (48 gate rows), K = 384 = [h|x].
// Thread: 2 rows x 1 unit (3 gates) x K-half, k-packed fma.rn.f32x2.
// ---------------------------------------------------------------------------

#define BATCH   256
#define IN_DIM  128
#define HID     256
#define STEPS   511

#define NCTA     256
#define NTHREADS 256
#define BM       16             // batch rows per group/CTA
#define NU       16             // hidden units per CTA
#define WSTR     388            // W row stride (floats): 1552B % 128 = 16
#define PSTR     772            // A row-pair stride (floats): 3088B % 128 = 16

// smem layout (float offsets)
#define OFF_W   0                           // 48 x WSTR
#define OFF_A   (48 * WSTR)                 // 18624: 8 pairs x PSTR
#define OFF_SC  (OFF_A + 8 * PSTR)          // 24800: 128 slots x 8 u64 (2048 f)
#define OFF_SB  (OFF_SC + 2048)             // 26848: biases (64)
#define OFF_WD  (OFF_SB + 64)               // 26912: W_dec (256)
#define SMEM_FLOATS (OFF_WD + 256)          // 27168
#define SMEM_BYTES  (SMEM_FLOATS * 4)       // 108672

typedef unsigned long long u64;

__device__ float    g_h[2][BATCH * HID];
__device__ unsigned g_arr[16 * 32];         // one counter per batch group

__global__ void gru_init_kernel(float* out) {
    int i = blockIdx.x * blockDim.x + threadIdx.x;
    if (i == 0) out[0] = 0.0f;
    if (i < 16 * 32) g_arr[i] = 0u;
    for (int j = i; j < BATCH * HID; j += gridDim.x * blockDim.x)
        g_h[0][j] = 0.0f;
}

__device__ __forceinline__ u64 ffma2(u64 a, u64 b, u64 c) {
    u64 d;
    asm("fma.rn.f32x2 %0, %1, %2, %3;" : "=l"(d) : "l"(a), "l"(b), "l"(c));
    return d;
}
__device__ __forceinline__ float up_sum(u64 u) {
    return __uint_as_float((unsigned)u) + __uint_as_float((unsigned)(u >> 32));
}
__device__ __forceinline__ float sigf(float v) { return 1.0f / (1.0f + __expf(-v)); }
__device__ __forceinline__ float tanhfast(float v) { return 2.0f * sigf(2.0f * v) - 1.0f; }

__device__ __forceinline__ unsigned ld_acq(const unsigned* p) {
    unsigned v;
    asm volatile("ld.acquire.gpu.global.u32 %0, [%1];" : "=r"(v) : "l"(p) : "memory");
    return v;
}

__global__ __launch_bounds__(NTHREADS, 2)
void gru_main_kernel(const float* __restrict__ x,
                     const float* __restrict__ gt,
                     const float* __restrict__ W_ih,
                     const float* __restrict__ W_hh,
                     const float* __restrict__ b_ih,
                     const float* __restrict__ b_hh,
                     const float* __restrict__ W_dec,
                     const float* __restrict__ b_dec,
                     float* __restrict__ out)
{
    extern __shared__ float smem[];
    float* sW  = smem + OFF_W;
    float* sA  = smem + OFF_A;
    u64*   sc  = (u64*)(smem + OFF_SC);
    float* sb  = smem + OFF_SB;
    float* sWd = smem + OFF_WD;

    const int tid  = threadIdx.x;
    const int cb   = blockIdx.x & 15;       // batch group (16 rows)
    const int cu   = blockIdx.x >> 4;       // unit group (16 units)
    const int B0   = cb * BM;
    const int U0   = cu * NU;

    const int lane = tid & 31;
    const int w    = tid >> 5;
    const int kh   = w & 1;                 // K-half: 0 -> k[0,192), 1 -> k[192,384)
    const int u_hi = w >> 1;                // 0..3
    const int rp   = lane & 7;              // row pair (rows 2rp, 2rp+1)
    const int u_lo = lane >> 3;             // 0..3
    const int u    = u_hi * 4 + u_lo;       // unit 0..15

    // ---- persistent W slice: 48 gate-rows x 384 k (k-major, no duplication)
    for (int idx = tid; idx < 48 * 384; idx += NTHREADS) {
        int c = idx / 384;
        int k = idx - c * 384;
        int g = c >> 4, uu = c & 15;
        int wrow = g * HID + U0 + uu;
        sW[c * WSTR + k] = (k < HID) ? W_hh[wrow * HID + k]
                                     : W_ih[wrow * IN_DIM + (k - HID)];
    }
    if (tid < 16) {
        sb[tid]      = b_ih[U0 + tid]           + b_hh[U0 + tid];        // r
        sb[16 + tid] = b_ih[HID + U0 + tid]     + b_hh[HID + U0 + tid];  // z
        sb[32 + tid] = b_ih[2 * HID + U0 + tid];                         // n (x)
        sb[48 + tid] = b_hh[2 * HID + U0 + tid];                         // n (h)
    }
    sWd[tid] = W_dec[tid];
    __syncthreads();

    const float bdec = b_dec[0];
    float loss_local = 0.0f;
    int p = 0;

    const ulonglong2* Ap = (const ulonglong2*)(sA + rp * PSTR);           // [2*k4 + j]
    const ulonglong2* Wr = (const ulonglong2*)(sW + (u)       * WSTR);
    const ulonglong2* Wz = (const ulonglong2*)(sW + (16 + u)  * WSTR);
    const ulonglong2* Wn = (const ulonglong2*)(sW + (32 + u)  * WSTR);
    u64* scp = sc + (u * 8 + rp) * 8;

    const unsigned* cnt = &g_arr[cb * 32];

    for (int t = 0; t < STEPS; ++t) {
        // ---- stage x(t) (k4 = 64..95): independent of h -> before the wait
        {
            int row  = tid >> 4;
            int c    = tid & 15;
            float* pairbase = sA + (row >> 1) * PSTR + (row & 1) * 4;
            const float* src = x + ((size_t)t * BATCH + B0 + row) * IN_DIM;
            #pragma unroll
            for (int q = 0; q < 2; ++q) {
                int col4 = c + 16 * q;
                float4 v = *(const float4*)(src + col4 * 4);
                *(float4*)(pairbase + (64 + col4) * 8) = v;
            }
        }

        // ---- wait for h(t) from sibling CTAs
        if (t > 0) {
            if (tid == 0) {
                unsigned target = (unsigned)t * 16u;
                while (ld_acq(cnt) < target) __nanosleep(20);
            }
            __syncthreads();
        }

        // ---- stage h(t) (k4 = 0..63), L1-bypassed loads
        {
            int row = tid >> 4;
            float* pairbase = sA + (row >> 1) * PSTR + (row & 1) * 4;
            const float4* src = (const float4*)(g_h[p] + (B0 + row) * HID);
            #pragma unroll
            for (int q = 0; q < 4; ++q) {
                int k4 = (tid & 15) + 16 * q;
                float4 v = __ldcg(src + k4);
                *(float4*)(pairbase + k4 * 8) = v;
            }
        }
        __syncthreads();

        // ---- loss for h(t) (this CTA handles global row B0+cu), gt[t]
        if (tid < 32 && t > 0) {
            const float* ap = sA + (cu >> 1) * PSTR + (cu & 1) * 4;
            float s = 0.0f;
            #pragma unroll
            for (int q = 0; q < 8; ++q) {
                int k = lane + 32 * q;
                s += ap[(k >> 2) * 8 + (k & 3)] * sWd[k];
            }
            #pragma unroll
            for (int sft = 16; sft > 0; sft >>= 1)
                s += __shfl_down_sync(0xffffffffu, s, sft);
            if (lane == 0) {
                float l = s + bdec;
                float g = gt[t * BATCH + B0 + cu];
                loss_local += fmaxf(l, 0.0f) + log1pf(__expf(-fabsf(l))) - g * l;
            }
        }

        // ---- GEMM: 2 rows x 3 gates x K-half, k-packed f32x2
        u64 r0 = 0, r1 = 0, z0 = 0, z1 = 0, nh0 = 0, nh1 = 0, ni0 = 0, ni1 = 0;

        #define STEP_K4(K4, N0, N1) {                                   \
            ulonglong2 a0 = Ap[2 * (K4)];                               \
            ulonglong2 a1 = Ap[2 * (K4) + 1];                           \
            ulonglong2 wr = Wr[K4], wz = Wz[K4], wn = Wn[K4];           \
            r0 = ffma2(a0.x, wr.x, r0);  r0 = ffma2(a0.y, wr.y, r0);    \
            r1 = ffma2(a1.x, wr.x, r1);  r1 = ffma2(a1.y, wr.y, r1);    \
            z0 = ffma2(a0.x, wz.x, z0);  z0 = ffma2(a0.y, wz.y, z0);    \
            z1 = ffma2(a1.x, wz.x, z1);  z1 = ffma2(a1.y, wz.y, z1);    \
            N0 = ffma2(a0.x, wn.x, N0);  N0 = ffma2(a0.y, wn.y, N0);    \
            N1 = ffma2(a1.x, wn.x, N1);  N1 = ffma2(a1.y, wn.y, N1); }

        if (kh == 0) {
            #pragma unroll 8
            for (int k4 = 0; k4 < 48; ++k4) STEP_K4(k4, nh0, nh1)
        } else {
            #pragma unroll 8
            for (int k4 = 48; k4 < 64; ++k4) STEP_K4(k4, nh0, nh1)
            #pragma unroll 8
            for (int k4 = 64; k4 < 96; ++k4) STEP_K4(k4, ni0, ni1)
        }
        #undef STEP_K4

        // ---- cross-half exchange
        if (kh == 1) {
            scp[0] = r0;  scp[1] = r1;  scp[2] = z0;  scp[3] = z1;
            scp[4] = nh0; scp[5] = nh1; scp[6] = ni0; scp[7] = ni1;
        }
        __syncthreads();

        // ---- epilogue (kh==0 warps): combine halves, gates, write h(t+1)
        if (kh == 0) {
            float rA = up_sum(r0)  + up_sum(scp[0]);
            float rB = up_sum(r1)  + up_sum(scp[1]);
            float zA = up_sum(z0)  + up_sum(scp[2]);
            float zB = up_sum(z1)  + up_sum(scp[3]);
            float hA = up_sum(nh0) + up_sum(scp[4]);
            float hB = up_sum(nh1) + up_sum(scp[5]);
            float iA = up_sum(ni0) + up_sum(scp[6]);
            float iB = up_sum(ni1) + up_sum(scp[7]);

            float br = sb[u], bz = sb[16 + u], bni = sb[32 + u], bnh = sb[48 + u];
            const float* pairbase = sA + rp * PSTR;
            int kidx = U0 + u;
            float hpA = pairbase[(kidx >> 2) * 8 + (kidx & 3)];
            float hpB = pairbase[(kidx >> 2) * 8 + 4 + (kidx & 3)];

            float rvA = sigf(rA + br), rvB = sigf(rB + br);
            float zvA = sigf(zA + bz), zvB = sigf(zB + bz);
            float nvA = tanhfast(iA + bni + rvA * (hA + bnh));
            float nvB = tanhfast(iB + bni + rvB * (hB + bnh));
            float hnA = nvA + zvA * (hpA - nvA);
            float hnB = nvB + zvB * (hpB - nvB);

            float* hdst = g_h[p ^ 1];
            hdst[(B0 + 2 * rp)     * HID + U0 + u] = hnA;
            hdst[(B0 + 2 * rp + 1) * HID + U0 + u] = hnB;
            __threadfence();
        }
        __syncthreads();
        if (tid == 0) atomicAdd((unsigned*)cnt, 1u);
        p ^= 1;
    }

    // ---- final-step loss for h(511), gt[511]
    if (tid == 0) {
        unsigned target = (unsigned)STEPS * 16u;
        while (ld_acq(cnt) < target) __nanosleep(20);
    }
    __syncthreads();
    if (tid < 32) {
        const float4* hr = (const float4*)(g_h[p] + (B0 + cu) * HID);
        float s = 0.0f;
        #pragma unroll
        for (int q = 0; q < 2; ++q) {
            int k4 = lane + 32 * q;
            float4 a = __ldcg(hr + k4);
            float4 wv = *(const float4*)(sWd + k4 * 4);
            s += a.x * wv.x + a.y * wv.y + a.z * wv.z + a.w * wv.w;
        }
        #pragma unroll
        for (int sft = 16; sft > 0; sft >>= 1)
            s += __shfl_down_sync(0xffffffffu, s, sft);
        if (lane == 0) {
            float l = s + bdec;
            float g = gt[(size_t)STEPS * BATCH + B0 + cu];
            loss_local += fmaxf(l, 0.0f) + log1pf(__expf(-fabsf(l))) - g * l;
        }
    }

    if (tid == 0) atomicAdd(out, loss_local);
}

extern "C" void kernel_launch(void* const* d_in, const int* in_sizes, int n_in,
                              void* d_out, int out_size) {
    const float* x     = (const float*)d_in[0];
    const float* gt    = (const float*)d_in[1];
    const float* W_ih  = (const float*)d_in[2];
    const float* W_hh  = (const float*)d_in[3];
    const float* b_ih  = (const float*)d_in[4];
    const float* b_hh  = (const float*)d_in[5];
    const float* W_dec = (const float*)d_in[6];
    const float* b_dec = (const float*)d_in[7];
    float* out = (float*)d_out;

    cudaFuncSetAttribute(gru_main_kernel,
                         cudaFuncAttributeMaxDynamicSharedMemorySize, SMEM_BYTES);

    gru_init_kernel<<<64, 256>>>(out);
    gru_main_kernel<<<NCTA, NTHREADS, SMEM_BYTES>>>(
        x, gt, W_ih, W_hh, b_ih, b_hh, W_dec, b_dec, out);
}

// round 7
// speedup vs baseline: 1.9776x; 1.3815x over previous
#include <cuda_runtime.h>

// ---------------------------------------------------------------------------
// GRU (511 steps) + BCE loss. Persistent, 256 CTAs (16 batch x 16 unit
// groups), 2 CTAs/SM. CTA: 16 rows x 16 units (48 gate rows), K=384 stored
// as 8 interleaved slices of [32 h | 16 x | 4 pad] floats (SLICE_F=52).
// Thread: 4 rows x 2 units x 3 gates x 1 K-slice; fma.rn.f32x2; K-reduction
// via 3-level shfl-xor reduce-scatter. lane = rq*8+ks, warp = unit-pair.
// ---------------------------------------------------------------------------

#define BATCH 256
#define IN_DIM 128
#define HID 256
#define STEPS 511
#define NCTA 256
#define NTHREADS 256
#define SLICE_F 52
#define ROW_F (8 * SLICE_F)              // 416 floats per logical row

#define OFF_W 0                          // 48 gate-rows
#define OFF_A (48 * ROW_F)               // 19968
#define OFF_SB (OFF_A + 16 * ROW_F)      // 26624
#define OFF_WD (OFF_SB + 64)             // 26688
#define SMEM_FLOATS (OFF_WD + 256)       // 26944
#define SMEM_BYTES (SMEM_FLOATS * 4)     // 107776

typedef unsigned long long u64;

__device__ float    g_h[2][BATCH * HID];
__device__ unsigned g_arr[16 * 32];

__global__ void gru_init_kernel(float* out) {
    int i = blockIdx.x * blockDim.x + threadIdx.x;
    if (i == 0) out[0] = 0.0f;
    if (i < 16 * 32) g_arr[i] = 0u;
    for (int j = i; j < BATCH * HID; j += gridDim.x * blockDim.x)
        g_h[0][j] = 0.0f;
}

__device__ __forceinline__ u64 ffma2(u64 a, u64 b, u64 c) {
    u64 d;
    asm("fma.rn.f32x2 %0, %1, %2, %3;" : "=l"(d) : "l"(a), "l"(b), "l"(c));
    return d;
}
__device__ __forceinline__ u64 addf2(u64 a, u64 b) {
    u64 d;
    asm("add.rn.f32x2 %0, %1, %2;" : "=l"(d) : "l"(a), "l"(b));
    return d;
}
__device__ __forceinline__ float sum2(u64 u) {
    return __uint_as_float((unsigned)u) + __uint_as_float((unsigned)(u >> 32));
}
__device__ __forceinline__ float sigf(float v) { return 1.0f / (1.0f + __expf(-v)); }
__device__ __forceinline__ unsigned ld_acq(const unsigned* p) {
    unsigned v;
    asm volatile("ld.acquire.gpu.global.u32 %0, [%1];" : "=r"(v) : "l"(p) : "memory");
    return v;
}

__global__ __launch_bounds__(NTHREADS, 2)
void gru_main_kernel(const float* __restrict__ x, const float* __restrict__ gt,
                     const float* __restrict__ W_ih, const float* __restrict__ W_hh,
                     const float* __restrict__ b_ih, const float* __restrict__ b_hh,
                     const float* __restrict__ W_dec, const float* __restrict__ b_dec,
                     float* __restrict__ out)
{
    extern __shared__ float smem[];
    float* sW  = smem + OFF_W;
    float* sA  = smem + OFF_A;
    float* sb  = smem + OFF_SB;
    float* sWd = smem + OFF_WD;

    const int tid = threadIdx.x;
    const int cb  = blockIdx.x & 15;
    const int cu  = blockIdx.x >> 4;
    const int B0  = cb * 16;
    const int U0  = cu * 16;

    const int lane = tid & 31;
    const int up   = tid >> 5;            // warp: units 2up, 2up+1
    const int ks   = lane & 7;            // K-slice
    const int rq   = lane >> 3;           // row-quad (rows 4rq..4rq+3)

    // ---- persistent W (48 gate-rows x 384 k, interleaved slices) + biases
    for (int idx = tid; idx < 48 * 384; idx += NTHREADS) {
        int gr = idx / 384, k = idx - gr * 384;
        int g = gr >> 4, uu = gr & 15, wrow = g * HID + U0 + uu;
        int s, o; float v;
        if (k < HID) { s = k >> 5; o = k & 31; v = W_hh[wrow * HID + k]; }
        else { int kx = k - HID; s = kx >> 4; o = 32 + (kx & 15); v = W_ih[wrow * IN_DIM + kx]; }
        sW[gr * ROW_F + s * SLICE_F + o] = v;
    }
    if (tid < 16) {
        sb[tid]      = b_ih[U0 + tid] + b_hh[U0 + tid];
        sb[16 + tid] = b_ih[HID + U0 + tid] + b_hh[HID + U0 + tid];
        sb[32 + tid] = b_ih[2 * HID + U0 + tid];
        sb[48 + tid] = b_hh[2 * HID + U0 + tid];
    }
    sWd[tid] = W_dec[tid];
    __syncthreads();

    const float bdec = b_dec[0];
    float loss_local = 0.0f;
    int p = 0;

    const ulonglong2* Ab = (const ulonglong2*)sA + rq * 4 * 104 + ks * 13;
    const ulonglong2* Wb = (const ulonglong2*)sW + up * 2 * 104 + ks * 13;
    const unsigned* cnt = &g_arr[cb * 32];

    for (int t = 0; t < STEPS; ++t) {
        u64 acc[4][2][4];                  // [r,z,nh,ni][u2][row j]
        #pragma unroll
        for (int g = 0; g < 4; ++g)
            #pragma unroll
            for (int u2 = 0; u2 < 2; ++u2)
                #pragma unroll
                for (int j = 0; j < 4; ++j) acc[g][u2][j] = 0ull;

        // ---- stage x(t) into slice x-regions
        {
            int row = tid >> 4;
            const float4* src = (const float4*)(x + ((size_t)t * BATCH + B0 + row) * IN_DIM);
            #pragma unroll
            for (int q = 0; q < 2; ++q) {
                int idx = (tid & 15) + 16 * q;       // float4 chunk 0..31
                float4 v = __ldg(src + idx);
                *(float4*)(sA + row * ROW_F + (idx >> 2) * SLICE_F + 32 + 4 * (idx & 3)) = v;
            }
        }
        __syncthreads();

        // ---- x-part GEMM (q4 = 8..11) before the barrier wait
        #pragma unroll
        for (int q4 = 8; q4 < 12; ++q4) {
            ulonglong2 a[4];
            #pragma unroll
            for (int j = 0; j < 4; ++j) a[j] = Ab[j * 104 + q4];
            #pragma unroll
            for (int u2 = 0; u2 < 2; ++u2)
                #pragma unroll
                for (int g = 0; g < 3; ++g) {
                    ulonglong2 wv = Wb[(g * 16 + u2) * 104 + q4];
                    int gi = (g == 2) ? 3 : g;
                    #pragma unroll
                    for (int j = 0; j < 4; ++j) {
                        acc[gi][u2][j] = ffma2(a[j].x, wv.x, acc[gi][u2][j]);
                        acc[gi][u2][j] = ffma2(a[j].y, wv.y, acc[gi][u2][j]);
                    }
                }
        }

        // ---- wait for h(t)
        if (t > 0) {
            if (tid == 0) {
                unsigned target = (unsigned)t * 16u;
                while (ld_acq(cnt) < target) __nanosleep(20);
            }
            __syncthreads();
        }

        // ---- stage h(t)
        {
            int row = tid >> 4;
            const float4* src = (const float4*)(g_h[p] + (B0 + row) * HID);
            #pragma unroll
            for (int q = 0; q < 4; ++q) {
                int idx = (tid & 15) + 16 * q;       // float4 chunk 0..63
                float4 v = __ldcg(src + idx);
                *(float4*)(sA + row * ROW_F + (idx >> 3) * SLICE_F + 4 * (idx & 7)) = v;
            }
        }
        __syncthreads();

        // ---- loss for h(t) (row B0+cu), warp 0
        if (tid < 32 && t > 0) {
            float s = 0.0f;
            #pragma unroll
            for (int q = 0; q < 8; ++q)
                s += sA[cu * ROW_F + q * SLICE_F + lane] * sWd[q * 32 + lane];
            #pragma unroll
            for (int sft = 16; sft > 0; sft >>= 1)
                s += __shfl_down_sync(0xffffffffu, s, sft);
            if (lane == 0) {
                float l = s + bdec;
                float g = gt[t * BATCH + B0 + cu];
                loss_local += fmaxf(l, 0.0f) + log1pf(__expf(-fabsf(l))) - g * l;
            }
        }

        // ---- h-part GEMM (q4 = 0..7)
        #pragma unroll
        for (int q4 = 0; q4 < 8; ++q4) {
            ulonglong2 a[4];
            #pragma unroll
            for (int j = 0; j < 4; ++j) a[j] = Ab[j * 104 + q4];
            #pragma unroll
            for (int u2 = 0; u2 < 2; ++u2)
                #pragma unroll
                for (int g = 0; g < 3; ++g) {
                    ulonglong2 wv = Wb[(g * 16 + u2) * 104 + q4];
                    #pragma unroll
                    for (int j = 0; j < 4; ++j) {
                        acc[g][u2][j] = ffma2(a[j].x, wv.x, acc[g][u2][j]);
                        acc[g][u2][j] = ffma2(a[j].y, wv.y, acc[g][u2][j]);
                    }
                }
        }

        // ---- reduce-scatter over the 8 ks lanes (owner: row ks&3, unit ks>>2)
        const int selu = ks >> 2, selj1 = (ks >> 1) & 1, selj0 = ks & 1;
        u64 w1[4][4], w2[4][2], w3[4];
        #pragma unroll
        for (int g = 0; g < 4; ++g)
            #pragma unroll
            for (int j = 0; j < 4; ++j) {
                u64 snd = selu ? acc[g][0][j] : acc[g][1][j];
                u64 rcv = __shfl_xor_sync(0xffffffffu, snd, 4);
                u64 kp  = selu ? acc[g][1][j] : acc[g][0][j];
                w1[g][j] = addf2(kp, rcv);
            }
        #pragma unroll
        for (int g = 0; g < 4; ++g)
            #pragma unroll
            for (int jj = 0; jj < 2; ++jj) {
                u64 snd = selj1 ? w1[g][jj] : w1[g][2 + jj];
                u64 rcv = __shfl_xor_sync(0xffffffffu, snd, 2);
                u64 kp  = selj1 ? w1[g][2 + jj] : w1[g][jj];
                w2[g][jj] = addf2(kp, rcv);
            }
        #pragma unroll
        for (int g = 0; g < 4; ++g) {
            u64 snd = selj0 ? w2[g][0] : w2[g][1];
            u64 rcv = __shfl_xor_sync(0xffffffffu, snd, 1);
            u64 kp  = selj0 ? w2[g][1] : w2[g][0];
            w3[g] = addf2(kp, rcv);
        }

        // ---- epilogue: one h element per thread
        {
            int orow  = rq * 4 + (ks & 3);
            int ounit = 2 * up + (ks >> 2);
            float rv = sigf(sum2(w3[0]) + sb[ounit]);
            float zv = sigf(sum2(w3[1]) + sb[16 + ounit]);
            float nh = sum2(w3[2]) + sb[48 + ounit];
            float ni = sum2(w3[3]) + sb[32 + ounit];
            float pre = ni + rv * nh;
            float nv = 2.0f * sigf(2.0f * pre) - 1.0f;    // tanh
            int kcol = U0 + ounit;
            float hp = sA[orow * ROW_F + (kcol >> 5) * SLICE_F + (kcol & 31)];
            float hn = nv + zv * (hp - nv);
            g_h[p ^ 1][(B0 + orow) * HID + kcol] = hn;
            __threadfence();
        }
        __syncthreads();
        if (tid == 0) atomicAdd((unsigned*)cnt, 1u);
        p ^= 1;
    }

    // ---- final loss: h(511), gt[511]
    if (tid == 0) {
        while (ld_acq(cnt) < (unsigned)STEPS * 16u) __nanosleep(20);
    }
    __syncthreads();
    if (tid < 32) {
        const float* hr = g_h[p] + (B0 + cu) * HID;
        float s = 0.0f;
        #pragma unroll
        for (int q = 0; q < 8; ++q) {
            int k = lane + 32 * q;
            s += __ldcg(hr + k) * sWd[k];
        }
        #pragma unroll
        for (int sft = 16; sft > 0; sft >>= 1)
            s += __shfl_down_sync(0xffffffffu, s, sft);
        if (lane == 0) {
            float l = s + bdec;
            float g = gt[(size_t)STEPS * BATCH + B0 + cu];
            loss_local += fmaxf(l, 0.0f) + log1pf(__expf(-fabsf(l))) - g * l;
        }
    }
    if (tid == 0) atomicAdd(out, loss_local);
}

extern "C" void kernel_launch(void* const* d_in, const int* in_sizes, int n_in,
                              void* d_out, int out_size) {
    const float* x     = (const float*)d_in[0];
    const float* gt    = (const float*)d_in[1];
    const float* W_ih  = (const float*)d_in[2];
    const float* W_hh  = (const float*)d_in[3];
    const float* b_ih  = (const float*)d_in[4];
    const float* b_hh  = (const float*)d_in[5];
    const float* W_dec = (const float*)d_in[6];
    const float* b_dec = (const float*)d_in[7];
    float* out = (float*)d_out;

    cudaFuncSetAttribute(gru_main_kernel,
                         cudaFuncAttributeMaxDynamicSharedMemorySize, SMEM_BYTES);

    gru_init_kernel<<<64, 256>>>(out);
    gru_main_kernel<<<NCTA, NTHREADS, SMEM_BYTES>>>(
        x, gt, W_ih, W_hh, b_ih, b_hh, W_dec, b_dec, out);
}